// round 3
// baseline (speedup 1.0000x reference)
#include <cuda_runtime.h>
#include <stdint.h>
#include <math.h>

#define D_MODEL 1024
#define T_SEQ   2048
#define BATCH   2
#define NROWS   (BATCH * T_SEQ)
#define DFF     4096
#define NHEADS  16
#define HDIM    64

// ---------------- scratch ----------------
__device__ __align__(16) float g_h   [NROWS * D_MODEL];
__device__ __align__(16) float g_qkv [NROWS * 3 * D_MODEL];
__device__ __align__(16) float g_attn[NROWS * D_MODEL];
__device__ __align__(16) float g_x1  [NROWS * D_MODEL];
__device__ __align__(16) float g_h2  [NROWS * D_MODEL];
__device__ __align__(16) float g_ff  [NROWS * DFF];
// rna-tf32 rounded weights: qkv_w | proj_w | mlp_w1 | mlp_w2
#define W_QKV  0
#define W_PROJ (D_MODEL * 3 * D_MODEL)
#define W_MLP1 (W_PROJ + D_MODEL * D_MODEL)
#define W_MLP2 (W_MLP1 + D_MODEL * DFF)
#define W_TOT  (W_MLP2 + DFF * D_MODEL)
__device__ __align__(16) float g_w[W_TOT];

// ---------------- helpers ----------------
__device__ __forceinline__ float to_tf32(float f) {
    uint32_t u;
    asm("cvt.rna.tf32.f32 %0, %1;" : "=r"(u) : "f"(f));
    return __uint_as_float(u);
}

__device__ __forceinline__ void mma_tf32(float* d,
                                         float a0, float a1, float a2, float a3,
                                         float b0, float b1) {
    asm volatile(
        "mma.sync.aligned.m16n8k8.row.col.f32.tf32.tf32.f32 "
        "{%0,%1,%2,%3}, {%4,%5,%6,%7}, {%8,%9}, {%0,%1,%2,%3};\n"
        : "+f"(d[0]), "+f"(d[1]), "+f"(d[2]), "+f"(d[3])
        : "r"(__float_as_uint(a0)), "r"(__float_as_uint(a1)),
          "r"(__float_as_uint(a2)), "r"(__float_as_uint(a3)),
          "r"(__float_as_uint(b0)), "r"(__float_as_uint(b1)));
}

__device__ __forceinline__ void cp16(uint32_t s, const float* g) {
    asm volatile("cp.async.cg.shared.global [%0], [%1], 16;\n" :: "r"(s), "l"(g));
}
__device__ __forceinline__ void cp_commit() { asm volatile("cp.async.commit_group;\n"); }
__device__ __forceinline__ void cp_wait1()  { asm volatile("cp.async.wait_group 1;\n"); }
__device__ __forceinline__ void cp_wait0()  { asm volatile("cp.async.wait_group 0;\n"); }

// ---------------- weight rna-tf32 conversion ----------------
__global__ void cvt_kernel(const float* __restrict__ src, float* __restrict__ dst, int n4) {
    const int i = blockIdx.x * blockDim.x + threadIdx.x;
    if (i < n4) {
        float4 v = reinterpret_cast<const float4*>(src)[i];
        v.x = to_tf32(v.x); v.y = to_tf32(v.y);
        v.z = to_tf32(v.z); v.w = to_tf32(v.w);
        reinterpret_cast<float4*>(dst)[i] = v;
    }
}

// ---------------- layernorm (rna-rounded output) ----------------
__global__ void ln_kernel(const float* __restrict__ x,
                          const float* __restrict__ g,
                          const float* __restrict__ b,
                          float* __restrict__ out) {
    const int row = blockIdx.x;
    const int tid = threadIdx.x;
    const float4 v = reinterpret_cast<const float4*>(x + (size_t)row * D_MODEL)[tid];
    float s  = v.x + v.y + v.z + v.w;
    float sq = v.x*v.x + v.y*v.y + v.z*v.z + v.w*v.w;

    __shared__ float rs[256];
    __shared__ float rq[256];
    rs[tid] = s; rq[tid] = sq;
    __syncthreads();
    #pragma unroll
    for (int st = 128; st > 0; st >>= 1) {
        if (tid < st) { rs[tid] += rs[tid + st]; rq[tid] += rq[tid + st]; }
        __syncthreads();
    }
    const float mean = rs[0] * (1.0f / D_MODEL);
    const float var  = rq[0] * (1.0f / D_MODEL) - mean * mean;
    const float rstd = rsqrtf(var + 1e-5f);

    const float4 gv = reinterpret_cast<const float4*>(g)[tid];
    const float4 bv = reinterpret_cast<const float4*>(b)[tid];
    float4 o;
    o.x = to_tf32((v.x - mean) * rstd * gv.x + bv.x);
    o.y = to_tf32((v.y - mean) * rstd * gv.y + bv.y);
    o.z = to_tf32((v.z - mean) * rstd * gv.z + bv.z);
    o.w = to_tf32((v.w - mean) * rstd * gv.w + bv.w);
    reinterpret_cast<float4*>(out + (size_t)row * D_MODEL)[tid] = o;
}

// ---------------- tf32 GEMM, cp.async double-buffered ----------------
// EPI: 0 = bias, round output; 1 = bias + exact GELU, round; 2 = bias + residual (fp32)
#define BM 128
#define BN 128
#define BK 32
#define AS_STRIDE 36
#define BS_STRIDE 136
#define A_TILE (BM * AS_STRIDE)
#define B_TILE (BK * BS_STRIDE)
#define GEMM_SMEM ((A_TILE + B_TILE) * 2 * 4)

template<int EPI>
__global__ void __launch_bounds__(256, 2)
gemm_tf32_kernel(const float* __restrict__ A, const float* __restrict__ B,
                 const float* __restrict__ bias, const float* __restrict__ res,
                 float* __restrict__ C, int M, int N, int K) {
    extern __shared__ float sm[];
    const uint32_t smem_u32 = (uint32_t)__cvta_generic_to_shared(sm);

    const int tid    = threadIdx.x;
    const int lane   = tid & 31;
    const int warp   = tid >> 5;
    const int warp_m = warp >> 1;
    const int warp_n = warp & 1;
    const int bm = blockIdx.y * BM;
    const int bn = blockIdx.x * BN;
    const int lg = lane >> 2;
    const int lt = lane & 3;

    float c[2][8][4];
    #pragma unroll
    for (int i = 0; i < 2; i++)
        #pragma unroll
        for (int j = 0; j < 8; j++)
            #pragma unroll
            for (int k = 0; k < 4; k++) c[i][j][k] = 0.0f;

    const int a_row = tid >> 3;
    const int a_col = (tid & 7) * 4;
    const int b_row = tid >> 5;
    const int b_col = (tid & 31) * 4;
    const int KT = K / BK;

    auto load_tile = [&](int k0, int st) {
        const uint32_t abase = smem_u32 + st * A_TILE * 4;
        const uint32_t bbase = smem_u32 + (2 * A_TILE + st * B_TILE) * 4;
        #pragma unroll
        for (int i = 0; i < 4; i++) {
            const int row = a_row + i * 32;
            cp16(abase + (row * AS_STRIDE + a_col) * 4,
                 &A[(size_t)(bm + row) * K + k0 + a_col]);
        }
        #pragma unroll
        for (int i = 0; i < 4; i++) {
            const int row = b_row + i * 8;
            cp16(bbase + (row * BS_STRIDE + b_col) * 4,
                 &B[(size_t)(k0 + row) * N + bn + b_col]);
        }
        cp_commit();
    };

    load_tile(0, 0);

    for (int kt = 0; kt < KT; kt++) {
        const int st = kt & 1;
        if (kt + 1 < KT) { load_tile((kt + 1) * BK, st ^ 1); cp_wait1(); }
        else             { cp_wait0(); }
        __syncthreads();

        const float* As = sm + st * A_TILE;
        const float* Bs = sm + 2 * A_TILE + st * B_TILE;

        #pragma unroll
        for (int ks = 0; ks < 4; ks++) {
            float af[2][4];
            #pragma unroll
            for (int mi = 0; mi < 2; mi++) {
                const int m = warp_m * 32 + mi * 16 + lg;
                const int k = ks * 8 + lt;
                af[mi][0] = As[m * AS_STRIDE + k];
                af[mi][1] = As[(m + 8) * AS_STRIDE + k];
                af[mi][2] = As[m * AS_STRIDE + k + 4];
                af[mi][3] = As[(m + 8) * AS_STRIDE + k + 4];
            }
            float bf[8][2];
            #pragma unroll
            for (int nt = 0; nt < 8; nt++) {
                const int n = warp_n * 64 + nt * 8 + lg;
                const int k = ks * 8 + lt;
                bf[nt][0] = Bs[k * BS_STRIDE + n];
                bf[nt][1] = Bs[(k + 4) * BS_STRIDE + n];
            }
            #pragma unroll
            for (int mi = 0; mi < 2; mi++)
                #pragma unroll
                for (int nt = 0; nt < 8; nt++)
                    mma_tf32(c[mi][nt], af[mi][0], af[mi][1], af[mi][2], af[mi][3],
                             bf[nt][0], bf[nt][1]);
        }
        __syncthreads();
    }

    #pragma unroll
    for (int mi = 0; mi < 2; mi++) {
        #pragma unroll
        for (int nt = 0; nt < 8; nt++) {
            const int col = bn + warp_n * 64 + nt * 8 + 2 * lt;
            const float b0 = bias[col], b1 = bias[col + 1];
            #pragma unroll
            for (int half = 0; half < 2; half++) {
                const int row = bm + warp_m * 32 + mi * 16 + lg + half * 8;
                float v0 = c[mi][nt][half * 2 + 0] + b0;
                float v1 = c[mi][nt][half * 2 + 1] + b1;
                if (EPI == 1) {
                    v0 = 0.5f * v0 * (1.0f + erff(v0 * 0.70710678118654752f));
                    v1 = 0.5f * v1 * (1.0f + erff(v1 * 0.70710678118654752f));
                } else if (EPI == 2) {
                    v0 += res[(size_t)row * N + col];
                    v1 += res[(size_t)row * N + col + 1];
                }
                if (EPI == 0 || EPI == 1) { v0 = to_tf32(v0); v1 = to_tf32(v1); }
                float2 o; o.x = v0; o.y = v1;
                *reinterpret_cast<float2*>(&C[(size_t)row * N + col]) = o;
            }
        }
    }
}

// ---------------- causal flash attention ----------------
#define AST 72
#define ATT_TILE (64 * AST)
#define ATT_SMEM (4 * ATT_TILE * 4)

__global__ void __launch_bounds__(256)
attn_kernel(const float* __restrict__ qkv, float* __restrict__ out) {
    extern __shared__ float sm[];
    const uint32_t smem_u32 = (uint32_t)__cvta_generic_to_shared(sm);

    const int tid  = threadIdx.x;
    const int lane = tid & 31;
    const int warp = tid >> 5;
    const int lg = lane >> 2;
    const int lt = lane & 3;

    const int qb = gridDim.x - 1 - blockIdx.x;
    const int bh = blockIdx.y;
    const int b  = bh >> 4;
    const int h  = bh & 15;
    const int q0 = qb * 128;
    const size_t rowbase = (size_t)b * T_SEQ;

    // stage Q (scale by 1/8 — exact in tf32 since inputs are pre-rounded)
    #pragma unroll
    for (int p = 0; p < 8; p++) {
        const int r = p * 16 + (tid >> 4);
        const int cc = (tid & 15) * 4;
        const float4 v = *reinterpret_cast<const float4*>(
            &qkv[(rowbase + q0 + r) * (size_t)(3 * D_MODEL) + h * HDIM + cc]);
        float4 o;
        o.x = v.x * 0.125f; o.y = v.y * 0.125f;
        o.z = v.z * 0.125f; o.w = v.w * 0.125f;
        *reinterpret_cast<float4*>(&sm[r * AST + cc]) = o;
    }
    __syncthreads();

    float qa[8][4];
    #pragma unroll
    for (int kt = 0; kt < 8; kt++) {
        const int m = warp * 16 + lg;
        const int k = kt * 8 + lt;
        qa[kt][0] = sm[m * AST + k];
        qa[kt][1] = sm[(m + 8) * AST + k];
        qa[kt][2] = sm[m * AST + k + 4];
        qa[kt][3] = sm[(m + 8) * AST + k + 4];
    }
    __syncthreads();

    const int kv_r = tid >> 4;
    const int kv_c = (tid & 15) * 4;

    auto prefetch = [&](int kb, int st) {
        const float* base = &qkv[(rowbase + (size_t)kb * 64) * (3 * D_MODEL) + h * HDIM];
        const uint32_t kb32 = smem_u32 + st * ATT_TILE * 4;
        const uint32_t vb32 = smem_u32 + (2 + st) * ATT_TILE * 4;
        #pragma unroll
        for (int i = 0; i < 4; i++) {
            const int r = kv_r + i * 16;
            cp16(kb32 + (r * AST + kv_c) * 4, base + (size_t)r * (3 * D_MODEL) + D_MODEL     + kv_c);
            cp16(vb32 + (r * AST + kv_c) * 4, base + (size_t)r * (3 * D_MODEL) + 2 * D_MODEL + kv_c);
        }
        cp_commit();
    };

    float o[8][4];
    #pragma unroll
    for (int i = 0; i < 8; i++)
        #pragma unroll
        for (int j = 0; j < 4; j++) o[i][j] = 0.0f;
    float m0 = -INFINITY, m1 = -INFINITY;
    float l0 = 0.0f, l1 = 0.0f;

    const int nkb = 2 * qb + 2;
    prefetch(0, 0);

    for (int kb = 0; kb < nkb; kb++) {
        const int st = kb & 1;
        if (kb + 1 < nkb) { prefetch(kb + 1, st ^ 1); cp_wait1(); }
        else              { cp_wait0(); }
        __syncthreads();

        const float* Ks = sm + st * ATT_TILE;
        const float* Vs = sm + (2 + st) * ATT_TILE;

        float s[8][4];
        #pragma unroll
        for (int i = 0; i < 8; i++)
            #pragma unroll
            for (int j = 0; j < 4; j++) s[i][j] = 0.0f;
        #pragma unroll
        for (int kt = 0; kt < 8; kt++) {
            const int k = kt * 8 + lt;
            #pragma unroll
            for (int nt = 0; nt < 8; nt++) {
                const int n = nt * 8 + lg;
                const float bb0 = Ks[n * AST + k];
                const float bb1 = Ks[n * AST + k + 4];
                mma_tf32(s[nt], qa[kt][0], qa[kt][1], qa[kt][2], qa[kt][3], bb0, bb1);
            }
        }

        const int t0 = kb * 64;
        if (t0 + 63 > q0 + warp * 16) {
            #pragma unroll
            for (int nt = 0; nt < 8; nt++) {
                #pragma unroll
                for (int j = 0; j < 4; j++) {
                    const int trow = q0 + warp * 16 + lg + (j >= 2 ? 8 : 0);
                    const int tcol = t0 + nt * 8 + 2 * lt + (j & 1);
                    if (tcol > trow) s[nt][j] = -INFINITY;
                }
            }
        }

        float mx0 = -INFINITY, mx1 = -INFINITY;
        #pragma unroll
        for (int nt = 0; nt < 8; nt++) {
            mx0 = fmaxf(mx0, fmaxf(s[nt][0], s[nt][1]));
            mx1 = fmaxf(mx1, fmaxf(s[nt][2], s[nt][3]));
        }
        mx0 = fmaxf(mx0, __shfl_xor_sync(0xffffffff, mx0, 1));
        mx0 = fmaxf(mx0, __shfl_xor_sync(0xffffffff, mx0, 2));
        mx1 = fmaxf(mx1, __shfl_xor_sync(0xffffffff, mx1, 1));
        mx1 = fmaxf(mx1, __shfl_xor_sync(0xffffffff, mx1, 2));
        const float mn0 = fmaxf(m0, mx0);
        const float mn1 = fmaxf(m1, mx1);

        float sum0 = 0.0f, sum1 = 0.0f;
        #pragma unroll
        for (int nt = 0; nt < 8; nt++) {
            s[nt][0] = __expf(s[nt][0] - mn0);
            s[nt][1] = __expf(s[nt][1] - mn0);
            s[nt][2] = __expf(s[nt][2] - mn1);
            s[nt][3] = __expf(s[nt][3] - mn1);
            sum0 += s[nt][0] + s[nt][1];
            sum1 += s[nt][2] + s[nt][3];
        }
        sum0 += __shfl_xor_sync(0xffffffff, sum0, 1);
        sum0 += __shfl_xor_sync(0xffffffff, sum0, 2);
        sum1 += __shfl_xor_sync(0xffffffff, sum1, 1);
        sum1 += __shfl_xor_sync(0xffffffff, sum1, 2);

        const float a0 = __expf(m0 - mn0);
        const float a1 = __expf(m1 - mn1);
        l0 = l0 * a0 + sum0;
        l1 = l1 * a1 + sum1;
        m0 = mn0; m1 = mn1;
        #pragma unroll
        for (int nt = 0; nt < 8; nt++) {
            o[nt][0] *= a0; o[nt][1] *= a0;
            o[nt][2] *= a1; o[nt][3] *= a1;
        }

        const int srcA = lg * 4 + (lt >> 1);
        const int srcB = srcA + 2;
        const bool odd = (lt & 1);
        #pragma unroll
        for (int kt = 0; kt < 8; kt++) {
            float x0 = __shfl_sync(0xffffffff, s[kt][0], srcA);
            float x1 = __shfl_sync(0xffffffff, s[kt][1], srcA);
            float y0 = __shfl_sync(0xffffffff, s[kt][2], srcA);
            float y1 = __shfl_sync(0xffffffff, s[kt][3], srcA);
            float z0 = __shfl_sync(0xffffffff, s[kt][0], srcB);
            float z1 = __shfl_sync(0xffffffff, s[kt][1], srcB);
            float w0 = __shfl_sync(0xffffffff, s[kt][2], srcB);
            float w1 = __shfl_sync(0xffffffff, s[kt][3], srcB);
            const float pa0 = to_tf32(odd ? x1 : x0);
            const float pa1 = to_tf32(odd ? y1 : y0);
            const float pa2 = to_tf32(odd ? z1 : z0);
            const float pa3 = to_tf32(odd ? w1 : w0);

            const int k = kt * 8 + lt;
            #pragma unroll
            for (int nt = 0; nt < 8; nt++) {
                const int n = nt * 8 + lg;
                const float bb0 = Vs[k * AST + n];
                const float bb1 = Vs[(k + 4) * AST + n];
                mma_tf32(o[nt], pa0, pa1, pa2, pa3, bb0, bb1);
            }
        }
        __syncthreads();
    }

    const float inv0 = 1.0f / l0;
    const float inv1 = 1.0f / l1;
    #pragma unroll
    for (int nt = 0; nt < 8; nt++) {
        const int dcol = h * HDIM + nt * 8 + 2 * lt;
        const size_t r0 = rowbase + q0 + warp * 16 + lg;
        float2 w0; w0.x = to_tf32(o[nt][0] * inv0); w0.y = to_tf32(o[nt][1] * inv0);
        float2 w1; w1.x = to_tf32(o[nt][2] * inv1); w1.y = to_tf32(o[nt][3] * inv1);
        *reinterpret_cast<float2*>(&out[r0 * D_MODEL + dcol])       = w0;
        *reinterpret_cast<float2*>(&out[(r0 + 8) * D_MODEL + dcol]) = w1;
    }
}

// ---------------- launch ----------------
extern "C" void kernel_launch(void* const* d_in, const int* in_sizes, int n_in,
                              void* d_out, int out_size) {
    const float* x      = (const float*)d_in[0];
    const float* ln1_g  = (const float*)d_in[1];
    const float* ln1_b  = (const float*)d_in[2];
    const float* qkv_w  = (const float*)d_in[3];
    const float* qkv_b  = (const float*)d_in[4];
    const float* proj_w = (const float*)d_in[5];
    const float* proj_b = (const float*)d_in[6];
    const float* ln2_g  = (const float*)d_in[7];
    const float* ln2_b  = (const float*)d_in[8];
    const float* mlp_w1 = (const float*)d_in[9];
    const float* mlp_b1 = (const float*)d_in[10];
    const float* mlp_w2 = (const float*)d_in[11];
    const float* mlp_b2 = (const float*)d_in[12];
    float* out = (float*)d_out;

    float *h, *qkv, *attn, *x1, *h2, *ff, *w;
    cudaGetSymbolAddress((void**)&h,    g_h);
    cudaGetSymbolAddress((void**)&qkv,  g_qkv);
    cudaGetSymbolAddress((void**)&attn, g_attn);
    cudaGetSymbolAddress((void**)&x1,   g_x1);
    cudaGetSymbolAddress((void**)&h2,   g_h2);
    cudaGetSymbolAddress((void**)&ff,   g_ff);
    cudaGetSymbolAddress((void**)&w,    g_w);

    cudaFuncSetAttribute(gemm_tf32_kernel<0>, cudaFuncAttributeMaxDynamicSharedMemorySize, GEMM_SMEM);
    cudaFuncSetAttribute(gemm_tf32_kernel<1>, cudaFuncAttributeMaxDynamicSharedMemorySize, GEMM_SMEM);
    cudaFuncSetAttribute(gemm_tf32_kernel<2>, cudaFuncAttributeMaxDynamicSharedMemorySize, GEMM_SMEM);
    cudaFuncSetAttribute(attn_kernel,         cudaFuncAttributeMaxDynamicSharedMemorySize, ATT_SMEM);

    // 0. rna-round weights once per graph replay
    cvt_kernel<<<(W_PROJ / 4 + 255) / 256 * 3, 256>>>(qkv_w,  w + W_QKV,  W_PROJ / 4 * 3);
    cvt_kernel<<<(W_PROJ / 4 + 255) / 256,     256>>>(proj_w, w + W_PROJ, W_PROJ / 4);
    cvt_kernel<<<(W_MLP2 - W_MLP1) / 4 / 256,  256>>>(mlp_w1, w + W_MLP1, (W_MLP2 - W_MLP1) / 4);
    cvt_kernel<<<(W_TOT - W_MLP2) / 4 / 256,   256>>>(mlp_w2, w + W_MLP2, (W_TOT - W_MLP2) / 4);

    // 1. LN1 (rounded output)
    ln_kernel<<<NROWS, 256>>>(x, ln1_g, ln1_b, h);
    // 2. QKV (rounded output)
    gemm_tf32_kernel<0><<<dim3(3 * D_MODEL / BN, NROWS / BM), 256, GEMM_SMEM>>>(
        h, w + W_QKV, qkv_b, nullptr, qkv, NROWS, 3 * D_MODEL, D_MODEL);
    // 3. attention (rounded output)
    attn_kernel<<<dim3(T_SEQ / 128, BATCH * NHEADS), 256, ATT_SMEM>>>(qkv, attn);
    // 4. x1 = x + attn @ proj_w + proj_b (fp32)
    gemm_tf32_kernel<2><<<dim3(D_MODEL / BN, NROWS / BM), 256, GEMM_SMEM>>>(
        attn, w + W_PROJ, proj_b, x, x1, NROWS, D_MODEL, D_MODEL);
    // 5. LN2 (rounded output)
    ln_kernel<<<NROWS, 256>>>(x1, ln2_g, ln2_b, h2);
    // 6. ff = gelu(h2 @ mlp_w1 + mlp_b1) (rounded output)
    gemm_tf32_kernel<1><<<dim3(DFF / BN, NROWS / BM), 256, GEMM_SMEM>>>(
        h2, w + W_MLP1, mlp_b1, nullptr, ff, NROWS, DFF, D_MODEL);
    // 7. out = x1 + ff @ mlp_w2 + mlp_b2 (fp32)
    gemm_tf32_kernel<2><<<dim3(D_MODEL / BN, NROWS / BM), 256, GEMM_SMEM>>>(
        ff, w + W_MLP2, mlp_b2, x1, out, NROWS, D_MODEL, DFF);
}

// round 4
// speedup vs baseline: 1.0333x; 1.0333x over previous
#include <cuda_runtime.h>
#include <stdint.h>
#include <math.h>

#define D_MODEL 1024
#define T_SEQ   2048
#define BATCH   2
#define NROWS   (BATCH * T_SEQ)
#define DFF     4096
#define NHEADS  16
#define HDIM    64

// ---------------- scratch ----------------
__device__ __align__(16) float g_h   [NROWS * D_MODEL];
__device__ __align__(16) float g_qkv [NROWS * 3 * D_MODEL];
__device__ __align__(16) float g_attn[NROWS * D_MODEL];
__device__ __align__(16) float g_x1  [NROWS * D_MODEL];
__device__ __align__(16) float g_h2  [NROWS * D_MODEL];
__device__ __align__(16) float g_ff  [NROWS * DFF];
// rna-tf32 rounded weights: qkv_w | proj_w | mlp_w1 | mlp_w2
#define SZ_QKV  (D_MODEL * 3 * D_MODEL)
#define SZ_PROJ (D_MODEL * D_MODEL)
#define SZ_MLP1 (D_MODEL * DFF)
#define SZ_MLP2 (DFF * D_MODEL)
#define W_QKV  0
#define W_PROJ (W_QKV + SZ_QKV)
#define W_MLP1 (W_PROJ + SZ_PROJ)
#define W_MLP2 (W_MLP1 + SZ_MLP1)
#define W_TOT  (W_MLP2 + SZ_MLP2)
__device__ __align__(16) float g_w[W_TOT];

// ---------------- helpers ----------------
__device__ __forceinline__ float to_tf32(float f) {
    uint32_t u;
    asm("cvt.rna.tf32.f32 %0, %1;" : "=r"(u) : "f"(f));
    return __uint_as_float(u);
}

__device__ __forceinline__ void mma_tf32(float* d,
                                         float a0, float a1, float a2, float a3,
                                         float b0, float b1) {
    asm volatile(
        "mma.sync.aligned.m16n8k8.row.col.f32.tf32.tf32.f32 "
        "{%0,%1,%2,%3}, {%4,%5,%6,%7}, {%8,%9}, {%0,%1,%2,%3};\n"
        : "+f"(d[0]), "+f"(d[1]), "+f"(d[2]), "+f"(d[3])
        : "r"(__float_as_uint(a0)), "r"(__float_as_uint(a1)),
          "r"(__float_as_uint(a2)), "r"(__float_as_uint(a3)),
          "r"(__float_as_uint(b0)), "r"(__float_as_uint(b1)));
}

__device__ __forceinline__ void cp16(uint32_t s, const float* g) {
    asm volatile("cp.async.cg.shared.global [%0], [%1], 16;\n" :: "r"(s), "l"(g));
}
__device__ __forceinline__ void cp_commit() { asm volatile("cp.async.commit_group;\n"); }
__device__ __forceinline__ void cp_wait1()  { asm volatile("cp.async.wait_group 1;\n"); }
__device__ __forceinline__ void cp_wait0()  { asm volatile("cp.async.wait_group 0;\n"); }

// ---------------- weight rna-tf32 conversion ----------------
__global__ void cvt_kernel(const float* __restrict__ src, float* __restrict__ dst, int n4) {
    const int i = blockIdx.x * blockDim.x + threadIdx.x;
    if (i < n4) {
        float4 v = reinterpret_cast<const float4*>(src)[i];
        v.x = to_tf32(v.x); v.y = to_tf32(v.y);
        v.z = to_tf32(v.z); v.w = to_tf32(v.w);
        reinterpret_cast<float4*>(dst)[i] = v;
    }
}

// ---------------- layernorm (rna-rounded output) ----------------
__global__ void ln_kernel(const float* __restrict__ x,
                          const float* __restrict__ g,
                          const float* __restrict__ b,
                          float* __restrict__ out) {
    const int row = blockIdx.x;
    const int tid = threadIdx.x;
    const float4 v = reinterpret_cast<const float4*>(x + (size_t)row * D_MODEL)[tid];
    float s  = v.x + v.y + v.z + v.w;
    float sq = v.x*v.x + v.y*v.y + v.z*v.z + v.w*v.w;

    __shared__ float rs[256];
    __shared__ float rq[256];
    rs[tid] = s; rq[tid] = sq;
    __syncthreads();
    #pragma unroll
    for (int st = 128; st > 0; st >>= 1) {
        if (tid < st) { rs[tid] += rs[tid + st]; rq[tid] += rq[tid + st]; }
        __syncthreads();
    }
    const float mean = rs[0] * (1.0f / D_MODEL);
    const float var  = rq[0] * (1.0f / D_MODEL) - mean * mean;
    const float rstd = rsqrtf(var + 1e-5f);

    const float4 gv = reinterpret_cast<const float4*>(g)[tid];
    const float4 bv = reinterpret_cast<const float4*>(b)[tid];
    float4 o;
    o.x = to_tf32((v.x - mean) * rstd * gv.x + bv.x);
    o.y = to_tf32((v.y - mean) * rstd * gv.y + bv.y);
    o.z = to_tf32((v.z - mean) * rstd * gv.z + bv.z);
    o.w = to_tf32((v.w - mean) * rstd * gv.w + bv.w);
    reinterpret_cast<float4*>(out + (size_t)row * D_MODEL)[tid] = o;
}

// ---------------- tf32 GEMM, cp.async double-buffered ----------------
#define BM 128
#define BN 128
#define BK 32
#define AS_STRIDE 36
#define BS_STRIDE 136
#define A_TILE (BM * AS_STRIDE)
#define B_TILE (BK * BS_STRIDE)
#define GEMM_SMEM ((A_TILE + B_TILE) * 2 * 4)

template<int EPI>
__global__ void __launch_bounds__(256, 2)
gemm_tf32_kernel(const float* __restrict__ A, const float* __restrict__ B,
                 const float* __restrict__ bias, const float* __restrict__ res,
                 float* __restrict__ C, int M, int N, int K) {
    extern __shared__ float sm[];
    const uint32_t smem_u32 = (uint32_t)__cvta_generic_to_shared(sm);

    const int tid    = threadIdx.x;
    const int lane   = tid & 31;
    const int warp   = tid >> 5;
    const int warp_m = warp >> 1;
    const int warp_n = warp & 1;
    const int bm = blockIdx.y * BM;
    const int bn = blockIdx.x * BN;
    const int lg = lane >> 2;
    const int lt = lane & 3;

    float c[2][8][4];
    #pragma unroll
    for (int i = 0; i < 2; i++)
        #pragma unroll
        for (int j = 0; j < 8; j++)
            #pragma unroll
            for (int k = 0; k < 4; k++) c[i][j][k] = 0.0f;

    const int a_row = tid >> 3;
    const int a_col = (tid & 7) * 4;
    const int b_row = tid >> 5;
    const int b_col = (tid & 31) * 4;
    const int KT = K / BK;

    auto load_tile = [&](int k0, int st) {
        const uint32_t abase = smem_u32 + st * A_TILE * 4;
        const uint32_t bbase = smem_u32 + (2 * A_TILE + st * B_TILE) * 4;
        #pragma unroll
        for (int i = 0; i < 4; i++) {
            const int row = a_row + i * 32;
            cp16(abase + (row * AS_STRIDE + a_col) * 4,
                 &A[(size_t)(bm + row) * K + k0 + a_col]);
        }
        #pragma unroll
        for (int i = 0; i < 4; i++) {
            const int row = b_row + i * 8;
            cp16(bbase + (row * BS_STRIDE + b_col) * 4,
                 &B[(size_t)(k0 + row) * N + bn + b_col]);
        }
        cp_commit();
    };

    load_tile(0, 0);

    for (int kt = 0; kt < KT; kt++) {
        const int st = kt & 1;
        if (kt + 1 < KT) { load_tile((kt + 1) * BK, st ^ 1); cp_wait1(); }
        else             { cp_wait0(); }
        __syncthreads();

        const float* As = sm + st * A_TILE;
        const float* Bs = sm + 2 * A_TILE + st * B_TILE;

        #pragma unroll
        for (int ks = 0; ks < 4; ks++) {
            float af[2][4];
            #pragma unroll
            for (int mi = 0; mi < 2; mi++) {
                const int m = warp_m * 32 + mi * 16 + lg;
                const int k = ks * 8 + lt;
                af[mi][0] = As[m * AS_STRIDE + k];
                af[mi][1] = As[(m + 8) * AS_STRIDE + k];
                af[mi][2] = As[m * AS_STRIDE + k + 4];
                af[mi][3] = As[(m + 8) * AS_STRIDE + k + 4];
            }
            float bf[8][2];
            #pragma unroll
            for (int nt = 0; nt < 8; nt++) {
                const int n = warp_n * 64 + nt * 8 + lg;
                const int k = ks * 8 + lt;
                bf[nt][0] = Bs[k * BS_STRIDE + n];
                bf[nt][1] = Bs[(k + 4) * BS_STRIDE + n];
            }
            #pragma unroll
            for (int mi = 0; mi < 2; mi++)
                #pragma unroll
                for (int nt = 0; nt < 8; nt++)
                    mma_tf32(c[mi][nt], af[mi][0], af[mi][1], af[mi][2], af[mi][3],
                             bf[nt][0], bf[nt][1]);
        }
        __syncthreads();
    }

    #pragma unroll
    for (int mi = 0; mi < 2; mi++) {
        #pragma unroll
        for (int nt = 0; nt < 8; nt++) {
            const int col = bn + warp_n * 64 + nt * 8 + 2 * lt;
            const float b0 = bias[col], b1 = bias[col + 1];
            #pragma unroll
            for (int half = 0; half < 2; half++) {
                const int row = bm + warp_m * 32 + mi * 16 + lg + half * 8;
                float v0 = c[mi][nt][half * 2 + 0] + b0;
                float v1 = c[mi][nt][half * 2 + 1] + b1;
                if (EPI == 1) {
                    v0 = 0.5f * v0 * (1.0f + erff(v0 * 0.70710678118654752f));
                    v1 = 0.5f * v1 * (1.0f + erff(v1 * 0.70710678118654752f));
                } else if (EPI == 2) {
                    v0 += res[(size_t)row * N + col];
                    v1 += res[(size_t)row * N + col + 1];
                }
                if (EPI == 0 || EPI == 1) { v0 = to_tf32(v0); v1 = to_tf32(v1); }
                float2 o; o.x = v0; o.y = v1;
                *reinterpret_cast<float2*>(&C[(size_t)row * N + col]) = o;
            }
        }
    }
}

// ---------------- causal flash attention v3: occ-2, Q in smem ----------------
// smem layout (floats):
//   Q  [128][QST]          at 0
//   K0,K1 [64][KST]        at QOFF
//   V0,V1 [64][VST]        at VOFF
#define QST 68
#define KST 68
#define VST 72
#define QOFF (128 * QST)                 // 8704
#define KTILE (64 * KST)                 // 4352
#define VOFF (QOFF + 2 * KTILE)          // 17408
#define VTILE (64 * VST)                 // 4608
#define ATT_SMEM ((VOFF + 2 * VTILE) * 4)  // 106496 bytes

__global__ void __launch_bounds__(256, 2)
attn_kernel(const float* __restrict__ qkv, float* __restrict__ out) {
    extern __shared__ float sm[];
    const uint32_t smem_u32 = (uint32_t)__cvta_generic_to_shared(sm);

    const int tid  = threadIdx.x;
    const int lane = tid & 31;
    const int warp = tid >> 5;          // 0..7, each 16 q-rows
    const int lg = lane >> 2;
    const int lt = lane & 3;

    const int qb = gridDim.x - 1 - blockIdx.x;   // heavy tiles first
    const int bh = blockIdx.y;
    const int b  = bh >> 4;
    const int h  = bh & 15;
    const int q0 = qb * 128;
    const size_t rowbase = (size_t)b * T_SEQ;

    // ---- stage Q (x0.125 exact; inputs pre-rounded tf32) ----
    #pragma unroll
    for (int p = 0; p < 8; p++) {
        const int r = p * 16 + (tid >> 4);
        const int cc = (tid & 15) * 4;
        const float4 v = *reinterpret_cast<const float4*>(
            &qkv[(rowbase + q0 + r) * (size_t)(3 * D_MODEL) + h * HDIM + cc]);
        float4 o;
        o.x = v.x * 0.125f; o.y = v.y * 0.125f;
        o.z = v.z * 0.125f; o.w = v.w * 0.125f;
        *reinterpret_cast<float4*>(&sm[r * QST + cc]) = o;
    }

    const int kv_r = tid >> 4;
    const int kv_c = (tid & 15) * 4;

    auto prefetch = [&](int kb, int st) {
        const float* base = &qkv[(rowbase + (size_t)kb * 64) * (3 * D_MODEL) + h * HDIM];
        const uint32_t kb32 = smem_u32 + (QOFF + st * KTILE) * 4;
        const uint32_t vb32 = smem_u32 + (VOFF + st * VTILE) * 4;
        #pragma unroll
        for (int i = 0; i < 4; i++) {
            const int r = kv_r + i * 16;
            cp16(kb32 + (r * KST + kv_c) * 4, base + (size_t)r * (3 * D_MODEL) + D_MODEL     + kv_c);
            cp16(vb32 + (r * VST + kv_c) * 4, base + (size_t)r * (3 * D_MODEL) + 2 * D_MODEL + kv_c);
        }
        cp_commit();
    };

    float o[8][4];
    #pragma unroll
    for (int i = 0; i < 8; i++)
        #pragma unroll
        for (int j = 0; j < 4; j++) o[i][j] = 0.0f;
    float m0 = -INFINITY, m1 = -INFINITY;
    float l0 = 0.0f, l1 = 0.0f;

    const int nkb = 2 * qb + 2;
    prefetch(0, 0);
    __syncthreads();   // Q staged (and covers first buffer ordering)

    const float* Qs = sm;
    const int qm = warp * 16 + lg;

    for (int kb = 0; kb < nkb; kb++) {
        const int st = kb & 1;
        if (kb + 1 < nkb) { prefetch(kb + 1, st ^ 1); cp_wait1(); }
        else              { cp_wait0(); }
        __syncthreads();

        const float* Ks = sm + QOFF + st * KTILE;
        const float* Vs = sm + VOFF + st * VTILE;

        // ---- S = Q K^T ----
        float s[8][4];
        #pragma unroll
        for (int i = 0; i < 8; i++)
            #pragma unroll
            for (int j = 0; j < 4; j++) s[i][j] = 0.0f;
        #pragma unroll
        for (int kt = 0; kt < 8; kt++) {
            const int k = kt * 8 + lt;
            const float a0 = Qs[qm * QST + k];
            const float a1 = Qs[(qm + 8) * QST + k];
            const float a2 = Qs[qm * QST + k + 4];
            const float a3 = Qs[(qm + 8) * QST + k + 4];
            #pragma unroll
            for (int nt = 0; nt < 8; nt++) {
                const int n = nt * 8 + lg;
                const float bb0 = Ks[n * KST + k];
                const float bb1 = Ks[n * KST + k + 4];
                mma_tf32(s[nt], a0, a1, a2, a3, bb0, bb1);
            }
        }

        // ---- causal mask (diagonal tiles only) ----
        const int t0 = kb * 64;
        if (t0 + 63 > q0 + warp * 16) {
            #pragma unroll
            for (int nt = 0; nt < 8; nt++) {
                #pragma unroll
                for (int j = 0; j < 4; j++) {
                    const int trow = q0 + warp * 16 + lg + (j >= 2 ? 8 : 0);
                    const int tcol = t0 + nt * 8 + 2 * lt + (j & 1);
                    if (tcol > trow) s[nt][j] = -INFINITY;
                }
            }
        }

        // ---- online softmax ----
        float mx0 = -INFINITY, mx1 = -INFINITY;
        #pragma unroll
        for (int nt = 0; nt < 8; nt++) {
            mx0 = fmaxf(mx0, fmaxf(s[nt][0], s[nt][1]));
            mx1 = fmaxf(mx1, fmaxf(s[nt][2], s[nt][3]));
        }
        mx0 = fmaxf(mx0, __shfl_xor_sync(0xffffffff, mx0, 1));
        mx0 = fmaxf(mx0, __shfl_xor_sync(0xffffffff, mx0, 2));
        mx1 = fmaxf(mx1, __shfl_xor_sync(0xffffffff, mx1, 1));
        mx1 = fmaxf(mx1, __shfl_xor_sync(0xffffffff, mx1, 2));
        const float mn0 = fmaxf(m0, mx0);
        const float mn1 = fmaxf(m1, mx1);

        float sum0 = 0.0f, sum1 = 0.0f;
        #pragma unroll
        for (int nt = 0; nt < 8; nt++) {
            s[nt][0] = __expf(s[nt][0] - mn0);
            s[nt][1] = __expf(s[nt][1] - mn0);
            s[nt][2] = __expf(s[nt][2] - mn1);
            s[nt][3] = __expf(s[nt][3] - mn1);
            sum0 += s[nt][0] + s[nt][1];
            sum1 += s[nt][2] + s[nt][3];
        }
        sum0 += __shfl_xor_sync(0xffffffff, sum0, 1);
        sum0 += __shfl_xor_sync(0xffffffff, sum0, 2);
        sum1 += __shfl_xor_sync(0xffffffff, sum1, 1);
        sum1 += __shfl_xor_sync(0xffffffff, sum1, 2);

        const float a0 = __expf(m0 - mn0);
        const float a1 = __expf(m1 - mn1);
        l0 = l0 * a0 + sum0;
        l1 = l1 * a1 + sum1;
        m0 = mn0; m1 = mn1;
        #pragma unroll
        for (int nt = 0; nt < 8; nt++) {
            o[nt][0] *= a0; o[nt][1] *= a0;
            o[nt][2] *= a1; o[nt][3] *= a1;
        }

        // ---- O += P @ V : repack c-layout -> a-layout via shuffles ----
        const int srcA = lg * 4 + (lt >> 1);
        const int srcB = srcA + 2;
        const bool odd = (lt & 1);
        #pragma unroll
        for (int kt = 0; kt < 8; kt++) {
            float x0 = __shfl_sync(0xffffffff, s[kt][0], srcA);
            float x1 = __shfl_sync(0xffffffff, s[kt][1], srcA);
            float y0 = __shfl_sync(0xffffffff, s[kt][2], srcA);
            float y1 = __shfl_sync(0xffffffff, s[kt][3], srcA);
            float z0 = __shfl_sync(0xffffffff, s[kt][0], srcB);
            float z1 = __shfl_sync(0xffffffff, s[kt][1], srcB);
            float w0 = __shfl_sync(0xffffffff, s[kt][2], srcB);
            float w1 = __shfl_sync(0xffffffff, s[kt][3], srcB);
            const float pa0 = to_tf32(odd ? x1 : x0);
            const float pa1 = to_tf32(odd ? y1 : y0);
            const float pa2 = to_tf32(odd ? z1 : z0);
            const float pa3 = to_tf32(odd ? w1 : w0);

            const int k = kt * 8 + lt;
            #pragma unroll
            for (int nt = 0; nt < 8; nt++) {
                const int n = nt * 8 + lg;
                const float bb0 = Vs[k * VST + n];
                const float bb1 = Vs[(k + 4) * VST + n];
                mma_tf32(o[nt], pa0, pa1, pa2, pa3, bb0, bb1);
            }
        }
        __syncthreads();
    }

    const float inv0 = 1.0f / l0;
    const float inv1 = 1.0f / l1;
    #pragma unroll
    for (int nt = 0; nt < 8; nt++) {
        const int dcol = h * HDIM + nt * 8 + 2 * lt;
        const size_t r0 = rowbase + q0 + warp * 16 + lg;
        float2 w0; w0.x = to_tf32(o[nt][0] * inv0); w0.y = to_tf32(o[nt][1] * inv0);
        float2 w1; w1.x = to_tf32(o[nt][2] * inv1); w1.y = to_tf32(o[nt][3] * inv1);
        *reinterpret_cast<float2*>(&out[r0 * D_MODEL + dcol])       = w0;
        *reinterpret_cast<float2*>(&out[(r0 + 8) * D_MODEL + dcol]) = w1;
    }
}

// ---------------- launch ----------------
extern "C" void kernel_launch(void* const* d_in, const int* in_sizes, int n_in,
                              void* d_out, int out_size) {
    const float* x      = (const float*)d_in[0];
    const float* ln1_g  = (const float*)d_in[1];
    const float* ln1_b  = (const float*)d_in[2];
    const float* qkv_w  = (const float*)d_in[3];
    const float* qkv_b  = (const float*)d_in[4];
    const float* proj_w = (const float*)d_in[5];
    const float* proj_b = (const float*)d_in[6];
    const float* ln2_g  = (const float*)d_in[7];
    const float* ln2_b  = (const float*)d_in[8];
    const float* mlp_w1 = (const float*)d_in[9];
    const float* mlp_b1 = (const float*)d_in[10];
    const float* mlp_w2 = (const float*)d_in[11];
    const float* mlp_b2 = (const float*)d_in[12];
    float* out = (float*)d_out;

    float *h, *qkv, *attn, *x1, *h2, *ff, *w;
    cudaGetSymbolAddress((void**)&h,    g_h);
    cudaGetSymbolAddress((void**)&qkv,  g_qkv);
    cudaGetSymbolAddress((void**)&attn, g_attn);
    cudaGetSymbolAddress((void**)&x1,   g_x1);
    cudaGetSymbolAddress((void**)&h2,   g_h2);
    cudaGetSymbolAddress((void**)&ff,   g_ff);
    cudaGetSymbolAddress((void**)&w,    g_w);

    cudaFuncSetAttribute(gemm_tf32_kernel<0>, cudaFuncAttributeMaxDynamicSharedMemorySize, GEMM_SMEM);
    cudaFuncSetAttribute(gemm_tf32_kernel<1>, cudaFuncAttributeMaxDynamicSharedMemorySize, GEMM_SMEM);
    cudaFuncSetAttribute(gemm_tf32_kernel<2>, cudaFuncAttributeMaxDynamicSharedMemorySize, GEMM_SMEM);
    cudaFuncSetAttribute(attn_kernel,         cudaFuncAttributeMaxDynamicSharedMemorySize, ATT_SMEM);

    // 0. rna-round weights (fixed element counts)
    cvt_kernel<<<SZ_QKV  / 4 / 256, 256>>>(qkv_w,  w + W_QKV,  SZ_QKV  / 4);
    cvt_kernel<<<SZ_PROJ / 4 / 256, 256>>>(proj_w, w + W_PROJ, SZ_PROJ / 4);
    cvt_kernel<<<SZ_MLP1 / 4 / 256, 256>>>(mlp_w1, w + W_MLP1, SZ_MLP1 / 4);
    cvt_kernel<<<SZ_MLP2 / 4 / 256, 256>>>(mlp_w2, w + W_MLP2, SZ_MLP2 / 4);

    // 1. LN1 (rounded output)
    ln_kernel<<<NROWS, 256>>>(x, ln1_g, ln1_b, h);
    // 2. QKV (rounded output)
    gemm_tf32_kernel<0><<<dim3(3 * D_MODEL / BN, NROWS / BM), 256, GEMM_SMEM>>>(
        h, w + W_QKV, qkv_b, nullptr, qkv, NROWS, 3 * D_MODEL, D_MODEL);
    // 3. attention (rounded output)
    attn_kernel<<<dim3(T_SEQ / 128, BATCH * NHEADS), 256, ATT_SMEM>>>(qkv, attn);
    // 4. x1 = x + attn @ proj_w + proj_b (fp32)
    gemm_tf32_kernel<2><<<dim3(D_MODEL / BN, NROWS / BM), 256, GEMM_SMEM>>>(
        attn, w + W_PROJ, proj_b, x, x1, NROWS, D_MODEL, D_MODEL);
    // 5. LN2 (rounded output)
    ln_kernel<<<NROWS, 256>>>(x1, ln2_g, ln2_b, h2);
    // 6. ff = gelu(h2 @ mlp_w1 + mlp_b1) (rounded output)
    gemm_tf32_kernel<1><<<dim3(DFF / BN, NROWS / BM), 256, GEMM_SMEM>>>(
        h2, w + W_MLP1, mlp_b1, nullptr, ff, NROWS, DFF, D_MODEL);
    // 7. out = x1 + ff @ mlp_w2 + mlp_b2 (fp32)
    gemm_tf32_kernel<2><<<dim3(D_MODEL / BN, NROWS / BM), 256, GEMM_SMEM>>>(
        ff, w + W_MLP2, mlp_b2, x1, out, NROWS, D_MODEL, DFF);
}